// round 14
// baseline (speedup 1.0000x reference)
#include <cuda_runtime.h>
#include <cuda_fp16.h>
#include <math.h>
#include <stdint.h>

// ---------------- problem constants ----------------
#define BB    4
#define LP    768
#define LS    50
#define LTOT  818
#define DD    2048
#define HH    8
#define HD    256
#define MV    8192
#define ME    4096
#define NTOK  (BB*LTOT)
#define SCALE_ 0.0625f

// ---------------- scratch ----------------
__device__ __half g_n  [NTOK*DD];
__device__ __half g_q  [NTOK*DD];
__device__ __half g_kb [NTOK*HD];
__device__ __half g_vb [NTOK*HD];
__device__ __half g_att[NTOK*DD];
__device__ __half g_mlp[(size_t)NTOK*MV];
__device__ __half g_wth[188743680ull];   // fp16 weights (orig layout [K][N])

// ---------------- helpers ----------------
__device__ __forceinline__ long rowmap(int r, int seg_len, int seg_off) {
    int b = r / seg_len;
    return (long)b * LTOT + seg_off + (r - b * seg_len);
}
__device__ __forceinline__ float gelu_tanh(float x) {
    float t = tanhf(0.7978845608028654f * (x + 0.044715f * x * x * x));
    return 0.5f * x * (1.0f + t);
}
__device__ __forceinline__ void cpa16(uint32_t dst, const void* src, int sz) {
    asm volatile("cp.async.ca.shared.global [%0], [%1], 16, %2;\n"
                 :: "r"(dst), "l"(src), "r"(sz));
}
#define CP_COMMIT() asm volatile("cp.async.commit_group;\n")
#define CP_WAIT2()  asm volatile("cp.async.wait_group 2;\n")
#define CP_WAIT1()  asm volatile("cp.async.wait_group 1;\n")
#define CP_WAIT0()  asm volatile("cp.async.wait_group 0;\n")

// fp16 mma, f32 accumulate
__device__ __forceinline__ void mma_f16(float* c, const uint32_t* a, const uint32_t* b) {
    asm volatile("mma.sync.aligned.m16n8k16.row.col.f32.f16.f16.f32 "
                 "{%0,%1,%2,%3}, {%4,%5,%6,%7}, {%8,%9}, {%0,%1,%2,%3};\n"
                 : "+f"(c[0]), "+f"(c[1]), "+f"(c[2]), "+f"(c[3])
                 : "r"(a[0]), "r"(a[1]), "r"(a[2]), "r"(a[3]),
                   "r"(b[0]), "r"(b[1]));
}
// tf32 mma (attention)
__device__ __forceinline__ void mma_tf32(float* c, const uint32_t* a, const uint32_t* b) {
    asm volatile("mma.sync.aligned.m16n8k8.row.col.f32.tf32.tf32.f32 "
                 "{%0,%1,%2,%3}, {%4,%5,%6,%7}, {%8,%9}, {%0,%1,%2,%3};\n"
                 : "+f"(c[0]), "+f"(c[1]), "+f"(c[2]), "+f"(c[3])
                 : "r"(a[0]), "r"(a[1]), "r"(a[2]), "r"(a[3]),
                   "r"(b[0]), "r"(b[1]));
}
__device__ __forceinline__ float tf32r(float x) {
    uint32_t u;
    asm("cvt.rna.tf32.f32 %0, %1;" : "=r"(u) : "f"(x));
    return __uint_as_float(u);
}
__device__ __forceinline__ void ldsm4(uint32_t* r, uint32_t addr) {
    asm volatile("ldmatrix.sync.aligned.m8n8.x4.shared.b16 {%0,%1,%2,%3}, [%4];\n"
                 : "=r"(r[0]), "=r"(r[1]), "=r"(r[2]), "=r"(r[3]) : "r"(addr));
}
__device__ __forceinline__ void ldsm4t(uint32_t* r, uint32_t addr) {
    asm volatile("ldmatrix.sync.aligned.m8n8.x4.trans.shared.b16 {%0,%1,%2,%3}, [%4];\n"
                 : "=r"(r[0]), "=r"(r[1]), "=r"(r[2]), "=r"(r[3]) : "r"(addr));
}
// convert 8 halfs (uint4) -> 8 floats
__device__ __forceinline__ void h8_to_f(uint4 u, float* f) {
    const __half2* hp = (const __half2*)&u;
    #pragma unroll
    for (int i = 0; i < 4; i++) {
        float2 t = __half22float2(hp[i]);
        f[2 * i] = t.x; f[2 * i + 1] = t.y;
    }
}

// ---------------- fused weight fp16 conversion (single launch) ----------------
struct RArgs {
    const float4* src[14];
    long cum[15];
};
__global__ void conv_w_all(RArgs ra, __half2* __restrict__ dst) {
    long total = ra.cum[14];
    for (long idx = blockIdx.x * (long)blockDim.x + threadIdx.x; idx < total;
         idx += (long)gridDim.x * blockDim.x) {
        int r = 0;
        while (idx >= ra.cum[r + 1]) ++r;
        float4 v = ra.src[r][idx - ra.cum[r]];
        dst[2 * idx]     = __floats2half2_rn(v.x, v.y);
        dst[2 * idx + 1] = __floats2half2_rn(v.z, v.w);
    }
}

// ---------------- init: copy prefix/suffix into h (=d_out) ----------------
__global__ void init_h_kernel(const float* __restrict__ prefix,
                              const float* __restrict__ suffix,
                              float* __restrict__ h) {
    int tok = blockIdx.x;
    int b = tok / LTOT, t = tok - b * LTOT;
    const float* src = (t < LP) ? prefix + ((size_t)(b * LP + t)) * DD
                                : suffix + ((size_t)(b * LS + (t - LP))) * DD;
    const float4* s4 = (const float4*)src;
    float4* dst = (float4*)(h + (size_t)tok * DD);
    dst[threadIdx.x]       = s4[threadIdx.x];
    dst[threadIdx.x + 256] = s4[threadIdx.x + 256];
}

// ---------------- rmsnorm (fp32 in, fp16 out: feeds GEMMs) ----------------
__global__ void rmsnorm_kernel(const float* __restrict__ x, __half2* __restrict__ out,
                               const float* __restrict__ wp, const float* __restrict__ we) {
    int tok = blockIdx.x;
    int t = tok % LTOT;
    const float* w = (t < LP) ? wp : we;
    const float4* xv = (const float4*)(x + (size_t)tok * DD);
    float4 v0 = xv[threadIdx.x];
    float4 v1 = xv[threadIdx.x + 256];
    float ss = v0.x*v0.x + v0.y*v0.y + v0.z*v0.z + v0.w*v0.w
             + v1.x*v1.x + v1.y*v1.y + v1.z*v1.z + v1.w*v1.w;
    __shared__ float red[8];
    #pragma unroll
    for (int o = 16; o; o >>= 1) ss += __shfl_xor_sync(0xffffffffu, ss, o);
    if ((threadIdx.x & 31) == 0) red[threadIdx.x >> 5] = ss;
    __syncthreads();
    float tot = red[0]+red[1]+red[2]+red[3]+red[4]+red[5]+red[6]+red[7];
    float sc = rsqrtf(tot * (1.0f / DD) + 1e-6f);
    const float4* wv = (const float4*)w;
    float4 w0 = wv[threadIdx.x];
    float4 w1 = wv[threadIdx.x + 256];
    __half2* ob = out + (size_t)tok * (DD / 2);
    ob[threadIdx.x * 2]           = __floats2half2_rn(v0.x*sc*(1.f+w0.x), v0.y*sc*(1.f+w0.y));
    ob[threadIdx.x * 2 + 1]       = __floats2half2_rn(v0.z*sc*(1.f+w0.z), v0.w*sc*(1.f+w0.w));
    ob[512 + threadIdx.x * 2]     = __floats2half2_rn(v1.x*sc*(1.f+w1.x), v1.y*sc*(1.f+w1.y));
    ob[512 + threadIdx.x * 2 + 1] = __floats2half2_rn(v1.z*sc*(1.f+w1.z), v1.w*sc*(1.f+w1.w));
}

// ---------------- RoPE (in-place on half q, k) ----------------
__global__ void rope_kernel(__half* __restrict__ q, __half* __restrict__ k) {
    int tok = blockIdx.x;
    int pos = tok % LTOT;
    for (int idx = threadIdx.x; idx < 9 * 128; idx += 256) {
        int head = idx >> 7, i = idx & 127;
        float inv = expf(-(float)i * (9.210340371976184f / 128.0f));
        float ang = (float)pos * inv;
        float c = cosf(ang), s = sinf(ang);
        __half* base = (head < HH) ? (q + (size_t)tok * DD + head * HD)
                                   : (k + (size_t)tok * HD);
        float x0 = __half2float(base[i]), x1 = __half2float(base[i + 128]);
        base[i]       = __float2half(x0 * c - x1 * s);
        base[i + 128] = __float2half(x1 * c + x0 * s);
    }
}

// ---------------- TF32 tensor-core attention (half I/O, unchanged) ----------------
#define AQ_LD 260
#define AK_LD 260
#define AV_LD 264
#define ASC_LD 836
#define QS_F (32*AQ_LD)
#define KV_F (64*AV_LD)
#define SC_F (32*ASC_LD)
#define ATTN_SMEM ((QS_F + KV_F + SC_F) * 4)

__global__ void __launch_bounds__(256, 1)
attn_mma(const __half* __restrict__ q, const __half* __restrict__ k,
         const __half* __restrict__ v, __half* __restrict__ att) {
    extern __shared__ float sm[];
    float* qs = sm;
    float* kv = sm + QS_F;
    float* sc = kv + KV_F;
    const uint32_t* qsu = (const uint32_t*)qs;
    const uint32_t* kvu = (const uint32_t*)kv;
    const uint32_t* scu = (const uint32_t*)sc;

    int b = blockIdx.z, h = blockIdx.y, qt = blockIdx.x;
    int t = threadIdx.x;
    int q0 = qt * 32;
    int warp = t >> 5, lane = t & 31;
    int wm = warp >> 2, wn = warp & 3;
    int lr = lane >> 2, lc = lane & 3;

    for (int i = t; i < 32 * 32; i += 256) {
        int qi = i >> 5, c8 = i & 31;
        int qg = q0 + qi;
        float f[8];
        if (qg < LTOT) {
            uint4 u = *(const uint4*)(q + ((size_t)(b * LTOT + qg)) * DD + h * HD + c8 * 8);
            h8_to_f(u, f);
        } else {
            #pragma unroll
            for (int j = 0; j < 8; j++) f[j] = 0.f;
        }
        float* dst = qs + qi * AQ_LD + c8 * 8;
        #pragma unroll
        for (int j = 0; j < 8; j++) dst[j] = f[j];
    }

    for (int kc = 0; kc < 13; kc++) {
        for (int i = t; i < 64 * 32; i += 256) {
            int kj = i >> 5, c8 = i & 31;
            int kg = kc * 64 + kj;
            float f[8];
            if (kg < LTOT) {
                uint4 u = *(const uint4*)(k + ((size_t)(b * LTOT + kg)) * HD + c8 * 8);
                h8_to_f(u, f);
            } else {
                #pragma unroll
                for (int j = 0; j < 8; j++) f[j] = 0.f;
            }
            float* dst = kv + kj * AK_LD + c8 * 8;
            #pragma unroll
            for (int j = 0; j < 8; j++) dst[j] = f[j];
        }
        __syncthreads();

        float s0[4] = {0.f, 0.f, 0.f, 0.f};
        float s1[4] = {0.f, 0.f, 0.f, 0.f};
        const uint32_t* qb = qsu + (wm * 16 + lr) * AQ_LD;
        const uint32_t* kb0 = kvu + (wn * 16 + lr) * AK_LD;
        const uint32_t* kb1 = kb0 + 8 * AK_LD;
        #pragma unroll
        for (int kq = 0; kq < 32; kq++) {
            int c = kq * 8 + lc;
            uint32_t a[4] = { qb[c], qb[8 * AQ_LD + c], qb[c + 4], qb[8 * AQ_LD + c + 4] };
            uint32_t b0[2] = { kb0[c], kb0[c + 4] };
            uint32_t b1[2] = { kb1[c], kb1[c + 4] };
            mma_tf32(s0, a, b0);
            mma_tf32(s1, a, b1);
        }
        int r0 = wm * 16 + lr, r1 = r0 + 8;
        int qg0 = q0 + r0, qg1 = q0 + r1;
        #pragma unroll
        for (int f = 0; f < 2; f++) {
            const float* s = f ? s1 : s0;
            int col = kc * 64 + wn * 16 + f * 8 + 2 * lc;
            #pragma unroll
            for (int cc = 0; cc < 2; cc++) {
                int kg = col + cc;
                bool allow = (kg < LP);
                sc[r0 * ASC_LD + kg] = (allow || kg <= qg0) ? s[cc]     * SCALE_ : -1e30f;
                sc[r1 * ASC_LD + kg] = (allow || kg <= qg1) ? s[cc + 2] * SCALE_ : -1e30f;
            }
        }
        __syncthreads();
    }

    {
        for (int j = 0; j < 4; j++) {
            float* row = sc + (warp * 4 + j) * ASC_LD;
            float mx = -1e30f;
            #pragma unroll 4
            for (int kk = lane; kk < 832; kk += 32) mx = fmaxf(mx, row[kk]);
            #pragma unroll
            for (int o = 16; o; o >>= 1) mx = fmaxf(mx, __shfl_xor_sync(0xffffffffu, mx, o));
            float sum = 0.f;
            #pragma unroll 4
            for (int kk = lane; kk < 832; kk += 32) {
                float e = expf(row[kk] - mx);
                row[kk] = e;
                sum += e;
            }
            #pragma unroll
            for (int o = 16; o; o >>= 1) sum += __shfl_xor_sync(0xffffffffu, sum, o);
            float invs = 1.0f / sum;
            #pragma unroll 4
            for (int kk = lane; kk < 832; kk += 32) row[kk] = tf32r(row[kk] * invs);
        }
    }
    __syncthreads();

    float o[8][4];
    #pragma unroll
    for (int ni = 0; ni < 8; ni++)
        #pragma unroll
        for (int j = 0; j < 4; j++) o[ni][j] = 0.f;

    for (int kc = 0; kc < 13; kc++) {
        for (int i = t; i < 64 * 32; i += 256) {
            int kj = i >> 5, c8 = i & 31;
            int kg = kc * 64 + kj;
            float f[8];
            if (kg < LTOT) {
                uint4 u = *(const uint4*)(v + ((size_t)(b * LTOT + kg)) * HD + c8 * 8);
                h8_to_f(u, f);
            } else {
                #pragma unroll
                for (int j = 0; j < 8; j++) f[j] = 0.f;
            }
            float* dst = kv + kj * AV_LD + c8 * 8;
            #pragma unroll
            for (int j = 0; j < 8; j++) dst[j] = f[j];
        }
        __syncthreads();

        const uint32_t* pb = scu + (wm * 16 + lr) * ASC_LD + kc * 64;
        #pragma unroll
        for (int kq = 0; kq < 8; kq++) {
            int c = kq * 8 + lc;
            uint32_t a[4] = { pb[c], pb[8 * ASC_LD + c], pb[c + 4], pb[8 * ASC_LD + c + 4] };
            const uint32_t* vb0 = kvu + (kq * 8 + lc) * AV_LD + wn * 64 + lr;
            const uint32_t* vb1 = vb0 + 4 * AV_LD;
            #pragma unroll
            for (int ni = 0; ni < 8; ni++) {
                uint32_t bfr[2] = { vb0[ni * 8], vb1[ni * 8] };
                mma_tf32(o[ni], a, bfr);
            }
        }
        __syncthreads();
    }

    int r0 = wm * 16 + lr, r1 = r0 + 8;
    int qg0 = q0 + r0, qg1 = q0 + r1;
    #pragma unroll
    for (int ni = 0; ni < 8; ni++) {
        int d = h * HD + wn * 64 + ni * 8 + 2 * lc;
        if (qg0 < LTOT)
            *(__half2*)(att + ((size_t)(b * LTOT + qg0)) * DD + d) =
                __floats2half2_rn(o[ni][0], o[ni][1]);
        if (qg1 < LTOT)
            *(__half2*)(att + ((size_t)(b * LTOT + qg1)) * DD + d) =
                __floats2half2_rn(o[ni][2], o[ni][3]);
    }
}

// ---------------- FP16 tensor-core GEMM ----------------
// BM=128, BN=128, BK=32, 128 threads (4 warps, 2m x 2n), warp tile 64x64.
// 3-stage cp.async pipeline; 2 CTAs/SM (regs ~214, smem 56.8KB/CTA).
// A rows padded to 80B; B rows padded to 272B (odd 16B-granule strides ->
// conflict-free ldmatrix / ldmatrix.trans).
// EPI 0: C(half) = acc; 1: C(float) += acc; 2: C(half) = gelu(G(half))*acc
#define A_LDB 80
#define B_LDB 272
#define A_BYT (128*A_LDB)              // 10240
#define STG_B (A_BYT + 32*B_LDB)       // 18944 bytes per stage
#define G5_SMEM (3*STG_B)              // 56832

struct GArgs {
    const __half* A;
    const __half* B[4];
    void*         C[4];
    const __half* G[4];
    int M[4], N[4], K[4], ldc[4], seg_len[4], seg_off[4];
    int lda;
};

template <int EPI>
__global__ void __launch_bounds__(128, 2)
gemm_f16(GArgs ga) {
    int z = blockIdx.z;
    int M = ga.M[z], N = ga.N[z], K = ga.K[z];
    int ldc = ga.ldc[z], seg_len = ga.seg_len[z], seg_off = ga.seg_off[z];
    int lda = ga.lda;
    int m0 = blockIdx.y * 128, n0 = blockIdx.x * 128;
    if (m0 >= M || n0 >= N) return;
    const __half* A  = ga.A;
    const __half* Bm = ga.B[z];
    const __half* G  = ga.G[z];

    extern __shared__ char smc[];
    uint32_t smb = (uint32_t)__cvta_generic_to_shared(smc);
    int t = threadIdx.x, warp = t >> 5, lane = t & 31;
    int wm = warp >> 1, wn = warp & 1;
    int lr = lane >> 2, lc = lane & 3;

    // staging geometry: A 128 rows x 4 chunks(16B): 1 thread/row, 4 chunks.
    //                   B 32 rows x 16 chunks: 4 threads/row, 4 chunks each.
    int ar = t;
    int br = t >> 2, bc = t & 3;
    int ra = m0 + ar;
    bool va = ra < M;
    long offA = va ? rowmap(ra, seg_len, seg_off) * (long)lda : 0;
    int szA = va ? 16 : 0;

    auto stage = [&](int k0, int buf) {
        uint32_t Ab = smb + (uint32_t)buf * STG_B;
        #pragma unroll
        for (int j = 0; j < 4; j++)
            cpa16(Ab + (uint32_t)ar * A_LDB + j * 16,
                  A + offA + k0 + j * 8, szA);
        uint32_t Bb = Ab + A_BYT;
        #pragma unroll
        for (int j = 0; j < 4; j++)
            cpa16(Bb + (uint32_t)br * B_LDB + (bc + 4 * j) * 16,
                  Bm + (size_t)(k0 + br) * N + n0 + (bc + 4 * j) * 8, 16);
        CP_COMMIT();
    };

    // ldmatrix lane address components
    int lrow = (lane & 7) + 8 * ((lane >> 3) & 1);
    int lhi  = (lane >> 4) & 1;

    float acc[4][8][4];
    #pragma unroll
    for (int mi = 0; mi < 4; mi++)
        #pragma unroll
        for (int ni = 0; ni < 8; ni++)
            #pragma unroll
            for (int j = 0; j < 4; j++) acc[mi][ni][j] = 0.f;

    int ntiles = K >> 5;
    stage(0, 0);
    stage(32, 1);

    for (int it = 0; it < ntiles; it++) {
        int nx = it + 2;
        if (nx < ntiles) {
            stage(nx << 5, nx % 3);
            CP_WAIT2();
        } else if (it + 1 < ntiles) {
            CP_WAIT1();
        } else {
            CP_WAIT0();
        }
        __syncthreads();

        uint32_t As = smb + (uint32_t)(it % 3) * STG_B;
        uint32_t Bs = As + A_BYT;
        #pragma unroll
        for (int kq = 0; kq < 2; kq++) {
            uint32_t af[4][4];
            #pragma unroll
            for (int mi = 0; mi < 4; mi++)
                ldsm4(af[mi], As + (uint32_t)(wm * 64 + mi * 16 + lrow) * A_LDB
                              + kq * 32 + lhi * 16);
            uint32_t bf[8][2];
            #pragma unroll
            for (int n2 = 0; n2 < 4; n2++) {
                uint32_t b4[4];
                ldsm4t(b4, Bs + (uint32_t)(kq * 16 + lrow) * B_LDB
                           + (uint32_t)(wn * 64 + n2 * 16 + lhi * 8) * 2);
                bf[n2 * 2][0] = b4[0]; bf[n2 * 2][1] = b4[1];
                bf[n2 * 2 + 1][0] = b4[2]; bf[n2 * 2 + 1][1] = b4[3];
            }
            #pragma unroll
            for (int mi = 0; mi < 4; mi++)
                #pragma unroll
                for (int ni = 0; ni < 8; ni++)
                    mma_f16(acc[mi][ni], af[mi], bf[ni]);
        }
        __syncthreads();
    }

    // epilogue
    #pragma unroll
    for (int mi = 0; mi < 4; mi++) {
        int rb = m0 + wm * 64 + mi * 16 + lr;
        #pragma unroll
        for (int hh = 0; hh < 2; hh++) {
            int r = rb + hh * 8;
            if (r >= M) continue;
            long base = rowmap(r, seg_len, seg_off) * (long)ldc + n0;
            #pragma unroll
            for (int ni = 0; ni < 8; ni++) {
                long p = base + wn * 64 + ni * 8 + lc * 2;
                float v0 = acc[mi][ni][hh * 2 + 0];
                float v1 = acc[mi][ni][hh * 2 + 1];
                if (EPI == 0) {
                    *(__half2*)((__half*)ga.C[z] + p) = __floats2half2_rn(v0, v1);
                } else if (EPI == 1) {
                    float* C = (float*)ga.C[z];
                    C[p] += v0; C[p + 1] += v1;
                } else {
                    __half2 gg = *(const __half2*)(G + p);
                    float2 gf = __half22float2(gg);
                    *(__half2*)((__half*)ga.C[z] + p) =
                        __floats2half2_rn(gelu_tanh(gf.x) * v0, gelu_tanh(gf.y) * v1);
                }
            }
        }
    }
}

// ---------------- host-side launch helper ----------------
struct SubProb {
    const __half* B; void* C; const __half* G;
    int M, N, K, ldc, seg_len, seg_off;
};

static void launch_gemm_multi(int epi, const __half* A, int lda,
                              const SubProb* sp, int nz) {
    GArgs ga;
    ga.A = A; ga.lda = lda;
    int maxN = 0, maxM = 0;
    for (int z = 0; z < nz; z++) {
        ga.B[z] = sp[z].B; ga.C[z] = sp[z].C; ga.G[z] = sp[z].G;
        ga.M[z] = sp[z].M; ga.N[z] = sp[z].N; ga.K[z] = sp[z].K;
        ga.ldc[z] = sp[z].ldc; ga.seg_len[z] = sp[z].seg_len; ga.seg_off[z] = sp[z].seg_off;
        if (sp[z].N > maxN) maxN = sp[z].N;
        if (sp[z].M > maxM) maxM = sp[z].M;
    }
    dim3 grid(maxN / 128, (maxM + 127) / 128, nz);
    if (epi == 0)      gemm_f16<0><<<grid, 128, G5_SMEM>>>(ga);
    else if (epi == 1) gemm_f16<1><<<grid, 128, G5_SMEM>>>(ga);
    else               gemm_f16<2><<<grid, 128, G5_SMEM>>>(ga);
}

extern "C" void kernel_launch(void* const* d_in, const int* in_sizes, int n_in,
                              void* d_out, int out_size) {
    const float* prefix = (const float*)d_in[0];
    const float* suffix = (const float*)d_in[1];
    const float* p_ln1  = (const float*)d_in[4];
    const float* p_ln2  = (const float*)d_in[9];
    const float* e_ln1  = (const float*)d_in[13];
    const float* e_ln2  = (const float*)d_in[18];

    const int W_IDX[14] = {5, 6, 7, 8, 10, 11, 12, 14, 15, 16, 17, 19, 20, 21};
    const size_t W_CNT[14] = {
        2ull*DD*DD, 2ull*DD*HD, 2ull*DD*HD, 2ull*DD*DD,
        2ull*DD*MV, 2ull*DD*MV, 2ull*MV*DD,
        2ull*DD*DD, 2ull*DD*HD, 2ull*DD*HD, 2ull*DD*DD,
        2ull*DD*ME, 2ull*DD*ME, 2ull*ME*DD
    };

    float* h = (float*)d_out;
    __half *n_, *q_, *k_, *v_, *att_, *mlp_, *wt_;
    cudaGetSymbolAddress((void**)&n_,   g_n);
    cudaGetSymbolAddress((void**)&q_,   g_q);
    cudaGetSymbolAddress((void**)&k_,   g_kb);
    cudaGetSymbolAddress((void**)&v_,   g_vb);
    cudaGetSymbolAddress((void**)&att_, g_att);
    cudaGetSymbolAddress((void**)&mlp_, g_mlp);
    cudaGetSymbolAddress((void**)&wt_,  g_wth);

    cudaFuncSetAttribute(attn_mma, cudaFuncAttributeMaxDynamicSharedMemorySize, ATTN_SMEM);
    cudaFuncSetAttribute(gemm_f16<0>, cudaFuncAttributeMaxDynamicSharedMemorySize, G5_SMEM);
    cudaFuncSetAttribute(gemm_f16<1>, cudaFuncAttributeMaxDynamicSharedMemorySize, G5_SMEM);
    cudaFuncSetAttribute(gemm_f16<2>, cudaFuncAttributeMaxDynamicSharedMemorySize, G5_SMEM);

    // convert all weights to fp16 (single fused launch)
    const __half* wt[14];
    {
        RArgs ra;
        long cum = 0;
        for (int i = 0; i < 14; i++) {
            ra.src[i] = (const float4*)d_in[W_IDX[i]];
            ra.cum[i] = cum;
            wt[i] = wt_ + cum * 4;
            cum += (long)(W_CNT[i] / 4);
        }
        ra.cum[14] = cum;
        conv_w_all<<<4096, 256>>>(ra, (__half2*)wt_);
    }
    const __half *tq_p = wt[0], *tk_p = wt[1], *tv_p = wt[2], *to_p = wt[3];
    const __half *tg_p = wt[4], *tu_p = wt[5], *td_p = wt[6];
    const __half *tq_e = wt[7], *tk_e = wt[8], *tv_e = wt[9], *to_e = wt[10];
    const __half *tg_e = wt[11], *tu_e = wt[12], *td_e = wt[13];

    init_h_kernel<<<NTOK, 256>>>(prefix, suffix, h);

    for (int layer = 0; layer < 2; layer++) {
        size_t lW  = (size_t)layer * DD * DD;
        size_t lKV = (size_t)layer * DD * HD;
        size_t lGp = (size_t)layer * DD * MV;
        size_t lGe = (size_t)layer * DD * ME;

        rmsnorm_kernel<<<NTOK, 256>>>(h, (__half2*)n_, p_ln1 + layer * DD, e_ln1 + layer * DD);

        {   // q projection (prefix + suffix)
            SubProb sp[2] = {
                { tq_p + lW, q_, nullptr, BB*LP, DD, DD, DD, LP, 0 },
                { tq_e + lW, q_, nullptr, BB*LS, DD, DD, DD, LS, LP } };
            launch_gemm_multi(0, n_, DD, sp, 2);
        }
        {   // k/v projections (4-way)
            SubProb sp[4] = {
                { tk_p + lKV, k_, nullptr, BB*LP, HD, DD, HD, LP, 0 },
                { tv_p + lKV, v_, nullptr, BB*LP, HD, DD, HD, LP, 0 },
                { tk_e + lKV, k_, nullptr, BB*LS, HD, DD, HD, LS, LP },
                { tv_e + lKV, v_, nullptr, BB*LS, HD, DD, HD, LS, LP } };
            launch_gemm_multi(0, n_, DD, sp, 4);
        }

        rope_kernel<<<NTOK, 256>>>(q_, k_);
        dim3 ag(26, HH, BB);
        attn_mma<<<ag, 256, ATTN_SMEM>>>(q_, k_, v_, att_);

        {   // o projection + residual (into float h)
            SubProb sp[2] = {
                { to_p + lW, h, nullptr, BB*LP, DD, DD, DD, LP, 0 },
                { to_e + lW, h, nullptr, BB*LS, DD, DD, DD, LS, LP } };
            launch_gemm_multi(1, att_, DD, sp, 2);
        }

        rmsnorm_kernel<<<NTOK, 256>>>(h, (__half2*)n_, p_ln2 + layer * DD, e_ln2 + layer * DD);

        {   // gate
            SubProb sp[2] = {
                { tg_p + lGp, mlp_, nullptr, BB*LP, MV, DD, MV, LP, 0 },
                { tg_e + lGe, mlp_, nullptr, BB*LS, ME, DD, MV, LS, LP } };
            launch_gemm_multi(0, n_, DD, sp, 2);
        }
        {   // up (fused gelu(gate)*up)
            SubProb sp[2] = {
                { tu_p + lGp, mlp_, mlp_, BB*LP, MV, DD, MV, LP, 0 },
                { tu_e + lGe, mlp_, mlp_, BB*LS, ME, DD, MV, LS, LP } };
            launch_gemm_multi(2, n_, DD, sp, 2);
        }
        {   // down + residual (into float h)
            SubProb sp[2] = {
                { td_p + lGp, h, nullptr, BB*LP, DD, MV, DD, LP, 0 },
                { td_e + lGe, h, nullptr, BB*LS, DD, ME, DD, LS, LP } };
            launch_gemm_multi(1, mlp_, MV, sp, 2);
        }
    }
}

// round 15
// speedup vs baseline: 1.2402x; 1.2402x over previous
#include <cuda_runtime.h>
#include <cuda_fp16.h>
#include <math.h>
#include <stdint.h>

// ---------------- problem constants ----------------
#define BB    4
#define LP    768
#define LS    50
#define LTOT  818
#define DD    2048
#define HH    8
#define HD    256
#define MV    8192
#define ME    4096
#define NTOK  (BB*LTOT)
#define SCALE_ 0.0625f

// ---------------- scratch ----------------
__device__ __half g_n  [NTOK*DD];
__device__ __half g_q  [NTOK*DD];
__device__ __half g_kb [NTOK*HD];
__device__ __half g_vb [NTOK*HD];
__device__ __half g_att[NTOK*DD];
__device__ __half g_mlp[(size_t)NTOK*MV];
__device__ __half g_wth[188743680ull];   // fp16 weights (orig layout [K][N])

// ---------------- helpers ----------------
__device__ __forceinline__ long rowmap(int r, int seg_len, int seg_off) {
    int b = r / seg_len;
    return (long)b * LTOT + seg_off + (r - b * seg_len);
}
__device__ __forceinline__ float gelu_tanh(float x) {
    float t = tanhf(0.7978845608028654f * (x + 0.044715f * x * x * x));
    return 0.5f * x * (1.0f + t);
}
__device__ __forceinline__ void cpa16(uint32_t dst, const void* src, int sz) {
    asm volatile("cp.async.ca.shared.global [%0], [%1], 16, %2;\n"
                 :: "r"(dst), "l"(src), "r"(sz));
}
#define CP_COMMIT() asm volatile("cp.async.commit_group;\n")
#define CP_WAIT1()  asm volatile("cp.async.wait_group 1;\n")
#define CP_WAIT0()  asm volatile("cp.async.wait_group 0;\n")

// fp16 mma, f32 accumulate
__device__ __forceinline__ void mma_f16(float* c, const uint32_t* a, const uint32_t* b) {
    asm volatile("mma.sync.aligned.m16n8k16.row.col.f32.f16.f16.f32 "
                 "{%0,%1,%2,%3}, {%4,%5,%6,%7}, {%8,%9}, {%0,%1,%2,%3};\n"
                 : "+f"(c[0]), "+f"(c[1]), "+f"(c[2]), "+f"(c[3])
                 : "r"(a[0]), "r"(a[1]), "r"(a[2]), "r"(a[3]),
                   "r"(b[0]), "r"(b[1]));
}
__device__ __forceinline__ void ldsm4(uint32_t* r, uint32_t addr) {
    asm volatile("ldmatrix.sync.aligned.m8n8.x4.shared.b16 {%0,%1,%2,%3}, [%4];\n"
                 : "=r"(r[0]), "=r"(r[1]), "=r"(r[2]), "=r"(r[3]) : "r"(addr));
}
__device__ __forceinline__ void ldsm4t(uint32_t* r, uint32_t addr) {
    asm volatile("ldmatrix.sync.aligned.m8n8.x4.trans.shared.b16 {%0,%1,%2,%3}, [%4];\n"
                 : "=r"(r[0]), "=r"(r[1]), "=r"(r[2]), "=r"(r[3]) : "r"(addr));
}

// ---------------- fused weight fp16 conversion (single launch) ----------------
struct RArgs {
    const float4* src[14];
    long cum[15];
};
__global__ void conv_w_all(RArgs ra, __half2* __restrict__ dst) {
    long total = ra.cum[14];
    for (long idx = blockIdx.x * (long)blockDim.x + threadIdx.x; idx < total;
         idx += (long)gridDim.x * blockDim.x) {
        int r = 0;
        while (idx >= ra.cum[r + 1]) ++r;
        float4 v = ra.src[r][idx - ra.cum[r]];
        dst[2 * idx]     = __floats2half2_rn(v.x, v.y);
        dst[2 * idx + 1] = __floats2half2_rn(v.z, v.w);
    }
}

// ---------------- init: copy prefix/suffix into h (=d_out) ----------------
__global__ void init_h_kernel(const float* __restrict__ prefix,
                              const float* __restrict__ suffix,
                              float* __restrict__ h) {
    int tok = blockIdx.x;
    int b = tok / LTOT, t = tok - b * LTOT;
    const float* src = (t < LP) ? prefix + ((size_t)(b * LP + t)) * DD
                                : suffix + ((size_t)(b * LS + (t - LP))) * DD;
    const float4* s4 = (const float4*)src;
    float4* dst = (float4*)(h + (size_t)tok * DD);
    dst[threadIdx.x]       = s4[threadIdx.x];
    dst[threadIdx.x + 256] = s4[threadIdx.x + 256];
}

// ---------------- rmsnorm (fp32 in, fp16 out: feeds GEMMs) ----------------
__global__ void rmsnorm_kernel(const float* __restrict__ x, __half2* __restrict__ out,
                               const float* __restrict__ wp, const float* __restrict__ we) {
    int tok = blockIdx.x;
    int t = tok % LTOT;
    const float* w = (t < LP) ? wp : we;
    const float4* xv = (const float4*)(x + (size_t)tok * DD);
    float4 v0 = xv[threadIdx.x];
    float4 v1 = xv[threadIdx.x + 256];
    float ss = v0.x*v0.x + v0.y*v0.y + v0.z*v0.z + v0.w*v0.w
             + v1.x*v1.x + v1.y*v1.y + v1.z*v1.z + v1.w*v1.w;
    __shared__ float red[8];
    #pragma unroll
    for (int o = 16; o; o >>= 1) ss += __shfl_xor_sync(0xffffffffu, ss, o);
    if ((threadIdx.x & 31) == 0) red[threadIdx.x >> 5] = ss;
    __syncthreads();
    float tot = red[0]+red[1]+red[2]+red[3]+red[4]+red[5]+red[6]+red[7];
    float sc = rsqrtf(tot * (1.0f / DD) + 1e-6f);
    const float4* wv = (const float4*)w;
    float4 w0 = wv[threadIdx.x];
    float4 w1 = wv[threadIdx.x + 256];
    __half2* ob = out + (size_t)tok * (DD / 2);
    ob[threadIdx.x * 2]           = __floats2half2_rn(v0.x*sc*(1.f+w0.x), v0.y*sc*(1.f+w0.y));
    ob[threadIdx.x * 2 + 1]       = __floats2half2_rn(v0.z*sc*(1.f+w0.z), v0.w*sc*(1.f+w0.w));
    ob[512 + threadIdx.x * 2]     = __floats2half2_rn(v1.x*sc*(1.f+w1.x), v1.y*sc*(1.f+w1.y));
    ob[512 + threadIdx.x * 2 + 1] = __floats2half2_rn(v1.z*sc*(1.f+w1.z), v1.w*sc*(1.f+w1.w));
}

// ---------------- RoPE (in-place on half q, k) ----------------
__global__ void rope_kernel(__half* __restrict__ q, __half* __restrict__ k) {
    int tok = blockIdx.x;
    int pos = tok % LTOT;
    for (int idx = threadIdx.x; idx < 9 * 128; idx += 256) {
        int head = idx >> 7, i = idx & 127;
        float inv = expf(-(float)i * (9.210340371976184f / 128.0f));
        float ang = (float)pos * inv;
        float c = cosf(ang), s = sinf(ang);
        __half* base = (head < HH) ? (q + (size_t)tok * DD + head * HD)
                                   : (k + (size_t)tok * HD);
        float x0 = __half2float(base[i]), x1 = __half2float(base[i + 128]);
        base[i]       = __float2half(x0 * c - x1 * s);
        base[i + 128] = __float2half(x1 * c + x0 * s);
    }
}

// ---------------- FP16 tensor-core attention ----------------
// 32 queries/block, 256 threads, 8 warps (2m x 4n).
// Half smem tiles; m16n8k16 mma for QK^T and P@V; fp32 softmax.
// Layout (bytes): Q 32x264h @0, KV 64x264h @16896, SC 32x836f @50688,
// P 32x840h @157696; total 211456.
#define AQH_LDB 528         // 264 halfs (33 granules, odd)
#define ASC_LD  836         // floats
#define APH_LDB 1680        // 840 halfs (105 granules, odd)
#define OFF_KV  16896
#define OFF_SC  50688
#define OFF_PH  157696
#define ATTN_SMEM 211456

__global__ void __launch_bounds__(256, 1)
attn_f16(const __half* __restrict__ q, const __half* __restrict__ k,
         const __half* __restrict__ v, __half* __restrict__ att) {
    extern __shared__ char smc[];
    __half* qh = (__half*)smc;
    __half* kvh = (__half*)(smc + OFF_KV);
    float* sc = (float*)(smc + OFF_SC);
    __half* ph = (__half*)(smc + OFF_PH);
    uint32_t smb = (uint32_t)__cvta_generic_to_shared(smc);
    uint32_t qh_s = smb, kv_s = smb + OFF_KV, ph_s = smb + OFF_PH;

    int b = blockIdx.z, h = blockIdx.y, qt = blockIdx.x;
    int t = threadIdx.x;
    int q0 = qt * 32;
    int warp = t >> 5, lane = t & 31;
    int wm = warp >> 2, wn = warp & 3;
    int lr = lane >> 2, lc = lane & 3;
    int lrow = (lane & 7) + 8 * ((lane >> 3) & 1);
    int lhi  = (lane >> 4) & 1;

    // load Q tile (32 rows x 256 halfs)
    for (int i = t; i < 32 * 32; i += 256) {
        int qi = i >> 5, c8 = i & 31;
        int qg = q0 + qi;
        uint4 u = (qg < LTOT)
            ? *(const uint4*)(q + ((size_t)(b * LTOT + qg)) * DD + h * HD + c8 * 8)
            : make_uint4(0, 0, 0, 0);
        *(uint4*)(qh + qi * 264 + c8 * 8) = u;
    }

    // ---- phase 1: S = Q @ K^T ----
    for (int kc = 0; kc < 13; kc++) {
        for (int i = t; i < 64 * 32; i += 256) {
            int kj = i >> 5, c8 = i & 31;
            int kg = kc * 64 + kj;
            uint4 u = (kg < LTOT)
                ? *(const uint4*)(k + ((size_t)(b * LTOT + kg)) * HD + c8 * 8)
                : make_uint4(0, 0, 0, 0);
            *(uint4*)(kvh + kj * 264 + c8 * 8) = u;
        }
        __syncthreads();

        float s0[4] = {0.f, 0.f, 0.f, 0.f};
        float s1[4] = {0.f, 0.f, 0.f, 0.f};
        uint32_t qa = qh_s + (uint32_t)(wm * 16 + lrow) * AQH_LDB + lhi * 16;
        uint32_t kb = kv_s + (uint32_t)(wn * 16 + lrow) * AQH_LDB + lhi * 16;
        #pragma unroll
        for (int ks = 0; ks < 16; ks++) {
            uint32_t a[4], bb[4];
            ldsm4(a, qa + ks * 32);
            ldsm4(bb, kb + ks * 32);
            uint32_t b0[2] = { bb[0], bb[2] };
            uint32_t b1[2] = { bb[1], bb[3] };
            mma_f16(s0, a, b0);
            mma_f16(s1, a, b1);
        }
        int r0 = wm * 16 + lr, r1 = r0 + 8;
        int qg0 = q0 + r0, qg1 = q0 + r1;
        #pragma unroll
        for (int f = 0; f < 2; f++) {
            const float* s = f ? s1 : s0;
            int col = kc * 64 + wn * 16 + f * 8 + 2 * lc;
            #pragma unroll
            for (int cc = 0; cc < 2; cc++) {
                int kg = col + cc;
                bool allow = (kg < LP);
                sc[r0 * ASC_LD + kg] = (allow || kg <= qg0) ? s[cc]     * SCALE_ : -1e30f;
                sc[r1 * ASC_LD + kg] = (allow || kg <= qg1) ? s[cc + 2] * SCALE_ : -1e30f;
            }
        }
        __syncthreads();
    }

    // ---- phase 2: softmax (fp32), write P as half ----
    {
        for (int j = 0; j < 4; j++) {
            int row_i = warp * 4 + j;
            float* row = sc + row_i * ASC_LD;
            __half* prow = ph + row_i * 840;
            float mx = -1e30f;
            #pragma unroll 4
            for (int kk = lane; kk < 832; kk += 32) mx = fmaxf(mx, row[kk]);
            #pragma unroll
            for (int o = 16; o; o >>= 1) mx = fmaxf(mx, __shfl_xor_sync(0xffffffffu, mx, o));
            float sum = 0.f;
            #pragma unroll 4
            for (int kk = lane; kk < 832; kk += 32) {
                float e = expf(row[kk] - mx);
                row[kk] = e;
                sum += e;
            }
            #pragma unroll
            for (int o = 16; o; o >>= 1) sum += __shfl_xor_sync(0xffffffffu, sum, o);
            float invs = 1.0f / sum;
            #pragma unroll 4
            for (int kk = lane; kk < 832; kk += 32)
                prow[kk] = __float2half(row[kk] * invs);
        }
    }
    __syncthreads();

    // ---- phase 3: O = P @ V ----
    float o[8][4];
    #pragma unroll
    for (int ni = 0; ni < 8; ni++)
        #pragma unroll
        for (int j = 0; j < 4; j++) o[ni][j] = 0.f;

    for (int kc = 0; kc < 13; kc++) {
        for (int i = t; i < 64 * 32; i += 256) {
            int kj = i >> 5, c8 = i & 31;
            int kg = kc * 64 + kj;
            uint4 u = (kg < LTOT)
                ? *(const uint4*)(v + ((size_t)(b * LTOT + kg)) * HD + c8 * 8)
                : make_uint4(0, 0, 0, 0);
            *(uint4*)(kvh + kj * 264 + c8 * 8) = u;
        }
        __syncthreads();

        uint32_t pa = ph_s + (uint32_t)(wm * 16 + lrow) * APH_LDB + kc * 128 + lhi * 16;
        #pragma unroll
        for (int ks = 0; ks < 4; ks++) {
            uint32_t a[4];
            ldsm4(a, pa + ks * 32);
            uint32_t vb = kv_s + (uint32_t)(ks * 16 + lrow) * AQH_LDB
                        + (uint32_t)(wn * 64 + lhi * 8) * 2;
            #pragma unroll
            for (int n2 = 0; n2 < 4; n2++) {
                uint32_t b4[4];
                ldsm4t(b4, vb + n2 * 32);
                uint32_t bf0[2] = { b4[0], b4[1] };
                uint32_t bf1[2] = { b4[2], b4[3] };
                mma_f16(o[n2 * 2], a, bf0);
                mma_f16(o[n2 * 2 + 1], a, bf1);
            }
        }
        __syncthreads();
    }

    int r0 = wm * 16 + lr, r1 = r0 + 8;
    int qg0 = q0 + r0, qg1 = q0 + r1;
    #pragma unroll
    for (int ni = 0; ni < 8; ni++) {
        int d = h * HD + wn * 64 + ni * 8 + 2 * lc;
        if (qg0 < LTOT)
            *(__half2*)(att + ((size_t)(b * LTOT + qg0)) * DD + d) =
                __floats2half2_rn(o[ni][0], o[ni][1]);
        if (qg1 < LTOT)
            *(__half2*)(att + ((size_t)(b * LTOT + qg1)) * DD + d) =
                __floats2half2_rn(o[ni][2], o[ni][3]);
    }
}

// ---------------- FP16 tensor-core GEMM (R11 config — best known) ----------------
// BM=128, BN=128, BK=32, 256 threads, 8 warps (2m x 4n), warp tile 64x32.
// 2-stage cp.async pipeline, 2 CTAs/SM.
#define A_LDB 80
#define B_LDB 272
#define STG_B (128*A_LDB + 32*B_LDB)   // 18944 bytes per stage
#define G5_SMEM (2*STG_B)

struct GArgs {
    const __half* A;
    const __half* B[4];
    void*         C[4];
    const __half* G[4];
    int M[4], N[4], K[4], ldc[4], seg_len[4], seg_off[4];
    int lda;
};

template <int EPI>
__global__ void __launch_bounds__(256, 2)
gemm_f16(GArgs ga) {
    int z = blockIdx.z;
    int M = ga.M[z], N = ga.N[z], K = ga.K[z];
    int ldc = ga.ldc[z], seg_len = ga.seg_len[z], seg_off = ga.seg_off[z];
    int lda = ga.lda;
    int m0 = blockIdx.y * 128, n0 = blockIdx.x * 128;
    if (m0 >= M || n0 >= N) return;
    const __half* A  = ga.A;
    const __half* Bm = ga.B[z];
    const __half* G  = ga.G[z];

    extern __shared__ char smc[];
    uint32_t smb = (uint32_t)__cvta_generic_to_shared(smc);
    int t = threadIdx.x, warp = t >> 5, lane = t & 31;
    int wm = warp >> 2, wn = warp & 3;
    int lr = lane >> 2, lc = lane & 3;

    int ar = t >> 2;
    int ac = t & 3;
    int br = t >> 3;
    int bc = t & 7;
    long offA[2]; int szA[2];
    #pragma unroll
    for (int j = 0; j < 2; j++) {
        int r = m0 + ar + 64 * j;
        bool v = r < M;
        offA[j] = v ? rowmap(r, seg_len, seg_off) * (long)lda : 0;
        szA[j] = v ? 16 : 0;
    }

    auto stage = [&](int k0, int buf) {
        uint32_t Ab = smb + (uint32_t)buf * STG_B;
        #pragma unroll
        for (int j = 0; j < 2; j++)
            cpa16(Ab + (uint32_t)(ar + 64 * j) * A_LDB + ac * 16,
                  A + offA[j] + k0 + ac * 8, szA[j]);
        uint32_t Bb = Ab + 128 * A_LDB;
        #pragma unroll
        for (int j = 0; j < 2; j++)
            cpa16(Bb + (uint32_t)br * B_LDB + (bc + 8 * j) * 16,
                  Bm + (size_t)(k0 + br) * N + n0 + (bc + 8 * j) * 8, 16);
        CP_COMMIT();
    };

    int lrow = (lane & 7) + 8 * ((lane >> 3) & 1);
    int lhi  = (lane >> 4) & 1;

    float acc[4][4][4];
    #pragma unroll
    for (int mi = 0; mi < 4; mi++)
        #pragma unroll
        for (int ni = 0; ni < 4; ni++)
            #pragma unroll
            for (int j = 0; j < 4; j++) acc[mi][ni][j] = 0.f;

    int ntiles = K >> 5;
    stage(0, 0);

    for (int it = 0; it < ntiles; it++) {
        if (it + 1 < ntiles) {
            stage((it + 1) << 5, (it + 1) & 1);
            CP_WAIT1();
        } else {
            CP_WAIT0();
        }
        __syncthreads();

        uint32_t As = smb + (uint32_t)(it & 1) * STG_B;
        uint32_t Bs = As + 128 * A_LDB;
        #pragma unroll
        for (int kq = 0; kq < 2; kq++) {
            uint32_t af[4][4];
            #pragma unroll
            for (int mi = 0; mi < 4; mi++)
                ldsm4(af[mi], As + (uint32_t)(wm * 64 + mi * 16 + lrow) * A_LDB
                              + kq * 32 + lhi * 16);
            uint32_t bf[4][2];
            #pragma unroll
            for (int n2 = 0; n2 < 2; n2++) {
                uint32_t b4[4];
                ldsm4t(b4, Bs + (uint32_t)(kq * 16 + lrow) * B_LDB
                           + (uint32_t)(wn * 32 + n2 * 16 + lhi * 8) * 2);
                bf[n2 * 2][0] = b4[0]; bf[n2 * 2][1] = b4[1];
                bf[n2 * 2 + 1][0] = b4[2]; bf[n2 * 2 + 1][1] = b4[3];
            }
            #pragma unroll
            for (int mi = 0; mi < 4; mi++)
                #pragma unroll
                for (int ni = 0; ni < 4; ni++)
                    mma_f16(acc[mi][ni], af[mi], bf[ni]);
        }
        __syncthreads();
    }

    #pragma unroll
    for (int mi = 0; mi < 4; mi++) {
        int rb = m0 + wm * 64 + mi * 16 + lr;
        #pragma unroll
        for (int hh = 0; hh < 2; hh++) {
            int r = rb + hh * 8;
            if (r >= M) continue;
            long base = rowmap(r, seg_len, seg_off) * (long)ldc + n0;
            #pragma unroll
            for (int ni = 0; ni < 4; ni++) {
                long p = base + wn * 32 + ni * 8 + lc * 2;
                float v0 = acc[mi][ni][hh * 2 + 0];
                float v1 = acc[mi][ni][hh * 2 + 1];
                if (EPI == 0) {
                    *(__half2*)((__half*)ga.C[z] + p) = __floats2half2_rn(v0, v1);
                } else if (EPI == 1) {
                    float* C = (float*)ga.C[z];
                    C[p] += v0; C[p + 1] += v1;
                } else {
                    __half2 gg = *(const __half2*)(G + p);
                    float2 gf = __half22float2(gg);
                    *(__half2*)((__half*)ga.C[z] + p) =
                        __floats2half2_rn(gelu_tanh(gf.x) * v0, gelu_tanh(gf.y) * v1);
                }
            }
        }
    }
}

// ---------------- host-side launch helper ----------------
struct SubProb {
    const __half* B; void* C; const __half* G;
    int M, N, K, ldc, seg_len, seg_off;
};

static void launch_gemm_multi(int epi, const __half* A, int lda,
                              const SubProb* sp, int nz) {
    GArgs ga;
    ga.A = A; ga.lda = lda;
    int maxN = 0, maxM = 0;
    for (int z = 0; z < nz; z++) {
        ga.B[z] = sp[z].B; ga.C[z] = sp[z].C; ga.G[z] = sp[z].G;
        ga.M[z] = sp[z].M; ga.N[z] = sp[z].N; ga.K[z] = sp[z].K;
        ga.ldc[z] = sp[z].ldc; ga.seg_len[z] = sp[z].seg_len; ga.seg_off[z] = sp[z].seg_off;
        if (sp[z].N > maxN) maxN = sp[z].N;
        if (sp[z].M > maxM) maxM = sp[z].M;
    }
    dim3 grid(maxN / 128, (maxM + 127) / 128, nz);
    if (epi == 0)      gemm_f16<0><<<grid, 256, G5_SMEM>>>(ga);
    else if (epi == 1) gemm_f16<1><<<grid, 256, G5_SMEM>>>(ga);
    else               gemm_f16<2><<<grid, 256, G5_SMEM>>>(ga);
}

extern "C" void kernel_launch(void* const* d_in, const int* in_sizes, int n_in,
                              void* d_out, int out_size) {
    const float* prefix = (const float*)d_in[0];
    const float* suffix = (const float*)d_in[1];
    const float* p_ln1  = (const float*)d_in[4];
    const float* p_ln2  = (const float*)d_in[9];
    const float* e_ln1  = (const float*)d_in[13];
    const float* e_ln2  = (const float*)d_in[18];

    const int W_IDX[14] = {5, 6, 7, 8, 10, 11, 12, 14, 15, 16, 17, 19, 20, 21};
    const size_t W_CNT[14] = {
        2ull*DD*DD, 2ull*DD*HD, 2ull*DD*HD, 2ull*DD*DD,
        2ull*DD*MV, 2ull*DD*MV, 2ull*MV*DD,
        2ull*DD*DD, 2ull*DD*HD, 2ull*DD*HD, 2ull*DD*DD,
        2ull*DD*ME, 2ull*DD*ME, 2ull*ME*DD
    };

    float* h = (float*)d_out;
    __half *n_, *q_, *k_, *v_, *att_, *mlp_, *wt_;
    cudaGetSymbolAddress((void**)&n_,   g_n);
    cudaGetSymbolAddress((void**)&q_,   g_q);
    cudaGetSymbolAddress((void**)&k_,   g_kb);
    cudaGetSymbolAddress((void**)&v_,   g_vb);
    cudaGetSymbolAddress((void**)&att_, g_att);
    cudaGetSymbolAddress((void**)&mlp_, g_mlp);
    cudaGetSymbolAddress((void**)&wt_,  g_wth);

    cudaFuncSetAttribute(attn_f16, cudaFuncAttributeMaxDynamicSharedMemorySize, ATTN_SMEM);
    cudaFuncSetAttribute(gemm_f16<0>, cudaFuncAttributeMaxDynamicSharedMemorySize, G5_SMEM);
    cudaFuncSetAttribute(gemm_f16<1>, cudaFuncAttributeMaxDynamicSharedMemorySize, G5_SMEM);
    cudaFuncSetAttribute(gemm_f16<2>, cudaFuncAttributeMaxDynamicSharedMemorySize, G5_SMEM);

    // convert all weights to fp16 (single fused launch)
    const __half* wt[14];
    {
        RArgs ra;
        long cum = 0;
        for (int i = 0; i < 14; i++) {
            ra.src[i] = (const float4*)d_in[W_IDX[i]];
            ra.cum[i] = cum;
            wt[i] = wt_ + cum * 4;
            cum += (long)(W_CNT[i] / 4);
        }
        ra.cum[14] = cum;
        conv_w_all<<<4096, 256>>>(ra, (__half2*)wt_);
    }
    const __half *tq_p = wt[0], *tk_p = wt[1], *tv_p = wt[2], *to_p = wt[3];
    const __half *tg_p = wt[4], *tu_p = wt[5], *td_p = wt[6];
    const __half *tq_e = wt[7], *tk_e = wt[8], *tv_e = wt[9], *to_e = wt[10];
    const __half *tg_e = wt[11], *tu_e = wt[12], *td_e = wt[13];

    init_h_kernel<<<NTOK, 256>>>(prefix, suffix, h);

    for (int layer = 0; layer < 2; layer++) {
        size_t lW  = (size_t)layer * DD * DD;
        size_t lKV = (size_t)layer * DD * HD;
        size_t lGp = (size_t)layer * DD * MV;
        size_t lGe = (size_t)layer * DD * ME;

        rmsnorm_kernel<<<NTOK, 256>>>(h, (__half2*)n_, p_ln1 + layer * DD, e_ln1 + layer * DD);

        {   // q projection (prefix + suffix)
            SubProb sp[2] = {
                { tq_p + lW, q_, nullptr, BB*LP, DD, DD, DD, LP, 0 },
                { tq_e + lW, q_, nullptr, BB*LS, DD, DD, DD, LS, LP } };
            launch_gemm_multi(0, n_, DD, sp, 2);
        }
        {   // k/v projections (4-way)
            SubProb sp[4] = {
                { tk_p + lKV, k_, nullptr, BB*LP, HD, DD, HD, LP, 0 },
                { tv_p + lKV, v_, nullptr, BB*LP, HD, DD, HD, LP, 0 },
                { tk_e + lKV, k_, nullptr, BB*LS, HD, DD, HD, LS, LP },
                { tv_e + lKV, v_, nullptr, BB*LS, HD, DD, HD, LS, LP } };
            launch_gemm_multi(0, n_, DD, sp, 4);
        }

        rope_kernel<<<NTOK, 256>>>(q_, k_);
        dim3 ag(26, HH, BB);
        attn_f16<<<ag, 256, ATTN_SMEM>>>(q_, k_, v_, att_);

        {   // o projection + residual (into float h)
            SubProb sp[2] = {
                { to_p + lW, h, nullptr, BB*LP, DD, DD, DD, LP, 0 },
                { to_e + lW, h, nullptr, BB*LS, DD, DD, DD, LS, LP } };
            launch_gemm_multi(1, att_, DD, sp, 2);
        }

        rmsnorm_kernel<<<NTOK, 256>>>(h, (__half2*)n_, p_ln2 + layer * DD, e_ln2 + layer * DD);

        {   // gate
            SubProb sp[2] = {
                { tg_p + lGp, mlp_, nullptr, BB*LP, MV, DD, MV, LP, 0 },
                { tg_e + lGe, mlp_, nullptr, BB*LS, ME, DD, MV, LS, LP } };
            launch_gemm_multi(0, n_, DD, sp, 2);
        }
        {   // up (fused gelu(gate)*up)
            SubProb sp[2] = {
                { tu_p + lGp, mlp_, mlp_, BB*LP, MV, DD, MV, LP, 0 },
                { tu_e + lGe, mlp_, mlp_, BB*LS, ME, DD, MV, LS, LP } };
            launch_gemm_multi(2, n_, DD, sp, 2);
        }
        {   // down + residual (into float h)
            SubProb sp[2] = {
                { td_p + lGp, h, nullptr, BB*LP, DD, MV, DD, LP, 0 },
                { td_e + lGe, h, nullptr, BB*LS, DD, ME, DD, LS, LP } };
            launch_gemm_multi(1, mlp_, MV, sp, 2);
        }
    }
}

// round 16
// speedup vs baseline: 1.4743x; 1.1887x over previous
#include <cuda_runtime.h>
#include <cuda_fp16.h>
#include <math.h>
#include <stdint.h>

// ---------------- problem constants ----------------
#define BB    4
#define LP    768
#define LS    50
#define LTOT  818
#define DD    2048
#define HH    8
#define HD    256
#define MV    8192
#define ME    4096
#define NTOK  (BB*LTOT)
#define SCALE_ 0.0625f

// ---------------- scratch ----------------
__device__ __half g_n  [NTOK*DD];
__device__ __half g_q  [NTOK*DD];
__device__ __half g_kb [NTOK*HD];
__device__ __half g_vb [NTOK*HD];
__device__ __half g_att[NTOK*DD];
__device__ __half g_mlp[(size_t)NTOK*MV];
__device__ __half g_wth[188743680ull];   // fp16 weights

// ---------------- helpers ----------------
__device__ __forceinline__ long rowmap(int r, int seg_len, int seg_off) {
    int b = r / seg_len;
    return (long)b * LTOT + seg_off + (r - b * seg_len);
}
__device__ __forceinline__ float gelu_tanh(float x) {
    float t = tanhf(0.7978845608028654f * (x + 0.044715f * x * x * x));
    return 0.5f * x * (1.0f + t);
}
__device__ __forceinline__ void cpa16(uint32_t dst, const void* src, int sz) {
    asm volatile("cp.async.ca.shared.global [%0], [%1], 16, %2;\n"
                 :: "r"(dst), "l"(src), "r"(sz));
}
#define CP_COMMIT() asm volatile("cp.async.commit_group;\n")
#define CP_WAIT1()  asm volatile("cp.async.wait_group 1;\n")
#define CP_WAIT0()  asm volatile("cp.async.wait_group 0;\n")

__device__ __forceinline__ void mma_f16(float* c, const uint32_t* a, const uint32_t* b) {
    asm volatile("mma.sync.aligned.m16n8k16.row.col.f32.f16.f16.f32 "
                 "{%0,%1,%2,%3}, {%4,%5,%6,%7}, {%8,%9}, {%0,%1,%2,%3};\n"
                 : "+f"(c[0]), "+f"(c[1]), "+f"(c[2]), "+f"(c[3])
                 : "r"(a[0]), "r"(a[1]), "r"(a[2]), "r"(a[3]),
                   "r"(b[0]), "r"(b[1]));
}
__device__ __forceinline__ void ldsm4(uint32_t* r, uint32_t addr) {
    asm volatile("ldmatrix.sync.aligned.m8n8.x4.shared.b16 {%0,%1,%2,%3}, [%4];\n"
                 : "=r"(r[0]), "=r"(r[1]), "=r"(r[2]), "=r"(r[3]) : "r"(addr));
}
__device__ __forceinline__ void ldsm4t(uint32_t* r, uint32_t addr) {
    asm volatile("ldmatrix.sync.aligned.m8n8.x4.trans.shared.b16 {%0,%1,%2,%3}, [%4];\n"
                 : "=r"(r[0]), "=r"(r[1]), "=r"(r[2]), "=r"(r[3]) : "r"(addr));
}

// ---------------- weight conversion ----------------
// Plain regions: region per blockIdx.y, contiguous fp32 -> fp16.
struct PlainArgs {
    const float4* src[10];
    long doff[10];     // dst offset in halfs
    long cnt4[10];     // float4 count
};
__global__ void conv_plain(PlainArgs pa, __half* __restrict__ wt) {
    int rg = blockIdx.y;
    const float4* s = pa.src[rg];
    __half* d = wt + pa.doff[rg];
    long n4 = pa.cnt4[rg];
    long stride = (long)gridDim.x * blockDim.x;
    for (long i = blockIdx.x * (long)blockDim.x + threadIdx.x; i < n4; i += stride) {
        float4 v = s[i];
        __half2* dd = (__half2*)(d + i * 4);
        dd[0] = __floats2half2_rn(v.x, v.y);
        dd[1] = __floats2half2_rn(v.z, v.w);
    }
}
// Gate/up interleave at 8-half-block granularity:
// dst row length 2*Mv: [g0..g7][u0..u7][g8..g15][u8..u15]...
__global__ void conv_gu(const float4* __restrict__ gsrc, const float4* __restrict__ usrc,
                        __half* __restrict__ dst, int mvShift /*log2(Mv)*/, long cnt4) {
    int sel = blockIdx.z;
    const float4* s = sel ? usrc : gsrc;
    long Mv = 1L << mvShift;
    long stride = (long)gridDim.x * blockDim.x;
    for (long i = blockIdx.x * (long)blockDim.x + threadIdx.x; i < cnt4; i += stride) {
        float4 v = s[i];
        long f = i * 4;
        long n = f & (Mv - 1);
        long row = f >> mvShift;
        long idx = row * (Mv << 1) + ((n >> 3) << 4) + sel * 8 + (n & 7);
        __half2* dd = (__half2*)(dst + idx);
        dd[0] = __floats2half2_rn(v.x, v.y);
        dd[1] = __floats2half2_rn(v.z, v.w);
    }
}

// ---------------- init: copy prefix/suffix into h (=d_out) ----------------
__global__ void init_h_kernel(const float* __restrict__ prefix,
                              const float* __restrict__ suffix,
                              float* __restrict__ h) {
    int tok = blockIdx.x;
    int b = tok / LTOT, t = tok - b * LTOT;
    const float* src = (t < LP) ? prefix + ((size_t)(b * LP + t)) * DD
                                : suffix + ((size_t)(b * LS + (t - LP))) * DD;
    const float4* s4 = (const float4*)src;
    float4* dst = (float4*)(h + (size_t)tok * DD);
    dst[threadIdx.x]       = s4[threadIdx.x];
    dst[threadIdx.x + 256] = s4[threadIdx.x + 256];
}

// ---------------- rmsnorm (fp32 in, fp16 out) ----------------
__global__ void rmsnorm_kernel(const float* __restrict__ x, __half2* __restrict__ out,
                               const float* __restrict__ wp, const float* __restrict__ we) {
    int tok = blockIdx.x;
    int t = tok % LTOT;
    const float* w = (t < LP) ? wp : we;
    const float4* xv = (const float4*)(x + (size_t)tok * DD);
    float4 v0 = xv[threadIdx.x];
    float4 v1 = xv[threadIdx.x + 256];
    float ss = v0.x*v0.x + v0.y*v0.y + v0.z*v0.z + v0.w*v0.w
             + v1.x*v1.x + v1.y*v1.y + v1.z*v1.z + v1.w*v1.w;
    __shared__ float red[8];
    #pragma unroll
    for (int o = 16; o; o >>= 1) ss += __shfl_xor_sync(0xffffffffu, ss, o);
    if ((threadIdx.x & 31) == 0) red[threadIdx.x >> 5] = ss;
    __syncthreads();
    float tot = red[0]+red[1]+red[2]+red[3]+red[4]+red[5]+red[6]+red[7];
    float sc = rsqrtf(tot * (1.0f / DD) + 1e-6f);
    const float4* wv = (const float4*)w;
    float4 w0 = wv[threadIdx.x];
    float4 w1 = wv[threadIdx.x + 256];
    __half2* ob = out + (size_t)tok * (DD / 2);
    ob[threadIdx.x * 2]           = __floats2half2_rn(v0.x*sc*(1.f+w0.x), v0.y*sc*(1.f+w0.y));
    ob[threadIdx.x * 2 + 1]       = __floats2half2_rn(v0.z*sc*(1.f+w0.z), v0.w*sc*(1.f+w0.w));
    ob[512 + threadIdx.x * 2]     = __floats2half2_rn(v1.x*sc*(1.f+w1.x), v1.y*sc*(1.f+w1.y));
    ob[512 + threadIdx.x * 2 + 1] = __floats2half2_rn(v1.z*sc*(1.f+w1.z), v1.w*sc*(1.f+w1.w));
}

// ---------------- RoPE (in-place on half q, k) ----------------
__global__ void rope_kernel(__half* __restrict__ q, __half* __restrict__ k) {
    int tok = blockIdx.x;
    int pos = tok % LTOT;
    for (int idx = threadIdx.x; idx < 9 * 128; idx += 256) {
        int head = idx >> 7, i = idx & 127;
        float inv = expf(-(float)i * (9.210340371976184f / 128.0f));
        float ang = (float)pos * inv;
        float c = cosf(ang), s = sinf(ang);
        __half* base = (head < HH) ? (q + (size_t)tok * DD + head * HD)
                                   : (k + (size_t)tok * HD);
        float x0 = __half2float(base[i]), x1 = __half2float(base[i + 128]);
        base[i]       = __float2half(x0 * c - x1 * s);
        base[i + 128] = __float2half(x1 * c + x0 * s);
    }
}

// ---------------- FP16 tensor-core attention (R15, unchanged) ----------------
#define AQH_LDB 528
#define ASC_LD  836
#define APH_LDB 1680
#define OFF_KV  16896
#define OFF_SC  50688
#define OFF_PH  157696
#define ATTN_SMEM 211456

__global__ void __launch_bounds__(256, 1)
attn_f16(const __half* __restrict__ q, const __half* __restrict__ k,
         const __half* __restrict__ v, __half* __restrict__ att) {
    extern __shared__ char smc[];
    __half* qh = (__half*)smc;
    __half* kvh = (__half*)(smc + OFF_KV);
    float* sc = (float*)(smc + OFF_SC);
    __half* ph = (__half*)(smc + OFF_PH);
    uint32_t smb = (uint32_t)__cvta_generic_to_shared(smc);
    uint32_t qh_s = smb, kv_s = smb + OFF_KV, ph_s = smb + OFF_PH;

    int b = blockIdx.z, h = blockIdx.y, qt = blockIdx.x;
    int t = threadIdx.x;
    int q0 = qt * 32;
    int warp = t >> 5, lane = t & 31;
    int wm = warp >> 2, wn = warp & 3;
    int lr = lane >> 2, lc = lane & 3;
    int lrow = (lane & 7) + 8 * ((lane >> 3) & 1);
    int lhi  = (lane >> 4) & 1;

    for (int i = t; i < 32 * 32; i += 256) {
        int qi = i >> 5, c8 = i & 31;
        int qg = q0 + qi;
        uint4 u = (qg < LTOT)
            ? *(const uint4*)(q + ((size_t)(b * LTOT + qg)) * DD + h * HD + c8 * 8)
            : make_uint4(0, 0, 0, 0);
        *(uint4*)(qh + qi * 264 + c8 * 8) = u;
    }

    for (int kc = 0; kc < 13; kc++) {
        for (int i = t; i < 64 * 32; i += 256) {
            int kj = i >> 5, c8 = i & 31;
            int kg = kc * 64 + kj;
            uint4 u = (kg < LTOT)
                ? *(const uint4*)(k + ((size_t)(b * LTOT + kg)) * HD + c8 * 8)
                : make_uint4(0, 0, 0, 0);
            *(uint4*)(kvh + kj * 264 + c8 * 8) = u;
        }
        __syncthreads();

        float s0[4] = {0.f, 0.f, 0.f, 0.f};
        float s1[4] = {0.f, 0.f, 0.f, 0.f};
        uint32_t qa = qh_s + (uint32_t)(wm * 16 + lrow) * AQH_LDB + lhi * 16;
        uint32_t kb = kv_s + (uint32_t)(wn * 16 + lrow) * AQH_LDB + lhi * 16;
        #pragma unroll
        for (int ks = 0; ks < 16; ks++) {
            uint32_t a[4], bb[4];
            ldsm4(a, qa + ks * 32);
            ldsm4(bb, kb + ks * 32);
            uint32_t b0[2] = { bb[0], bb[2] };
            uint32_t b1[2] = { bb[1], bb[3] };
            mma_f16(s0, a, b0);
            mma_f16(s1, a, b1);
        }
        int r0 = wm * 16 + lr, r1 = r0 + 8;
        int qg0 = q0 + r0, qg1 = q0 + r1;
        #pragma unroll
        for (int f = 0; f < 2; f++) {
            const float* s = f ? s1 : s0;
            int col = kc * 64 + wn * 16 + f * 8 + 2 * lc;
            #pragma unroll
            for (int cc = 0; cc < 2; cc++) {
                int kg = col + cc;
                bool allow = (kg < LP);
                sc[r0 * ASC_LD + kg] = (allow || kg <= qg0) ? s[cc]     * SCALE_ : -1e30f;
                sc[r1 * ASC_LD + kg] = (allow || kg <= qg1) ? s[cc + 2] * SCALE_ : -1e30f;
            }
        }
        __syncthreads();
    }

    {
        for (int j = 0; j < 4; j++) {
            int row_i = warp * 4 + j;
            float* row = sc + row_i * ASC_LD;
            __half* prow = ph + row_i * 840;
            float mx = -1e30f;
            #pragma unroll 4
            for (int kk = lane; kk < 832; kk += 32) mx = fmaxf(mx, row[kk]);
            #pragma unroll
            for (int o = 16; o; o >>= 1) mx = fmaxf(mx, __shfl_xor_sync(0xffffffffu, mx, o));
            float sum = 0.f;
            #pragma unroll 4
            for (int kk = lane; kk < 832; kk += 32) {
                float e = expf(row[kk] - mx);
                row[kk] = e;
                sum += e;
            }
            #pragma unroll
            for (int o = 16; o; o >>= 1) sum += __shfl_xor_sync(0xffffffffu, sum, o);
            float invs = 1.0f / sum;
            #pragma unroll 4
            for (int kk = lane; kk < 832; kk += 32)
                prow[kk] = __float2half(row[kk] * invs);
        }
    }
    __syncthreads();

    float o[8][4];
    #pragma unroll
    for (int ni = 0; ni < 8; ni++)
        #pragma unroll
        for (int j = 0; j < 4; j++) o[ni][j] = 0.f;

    for (int kc = 0; kc < 13; kc++) {
        for (int i = t; i < 64 * 32; i += 256) {
            int kj = i >> 5, c8 = i & 31;
            int kg = kc * 64 + kj;
            uint4 u = (kg < LTOT)
                ? *(const uint4*)(v + ((size_t)(b * LTOT + kg)) * HD + c8 * 8)
                : make_uint4(0, 0, 0, 0);
            *(uint4*)(kvh + kj * 264 + c8 * 8) = u;
        }
        __syncthreads();

        uint32_t pa = ph_s + (uint32_t)(wm * 16 + lrow) * APH_LDB + kc * 128 + lhi * 16;
        #pragma unroll
        for (int ks = 0; ks < 4; ks++) {
            uint32_t a[4];
            ldsm4(a, pa + ks * 32);
            uint32_t vb = kv_s + (uint32_t)(ks * 16 + lrow) * AQH_LDB
                        + (uint32_t)(wn * 64 + lhi * 8) * 2;
            #pragma unroll
            for (int n2 = 0; n2 < 4; n2++) {
                uint32_t b4[4];
                ldsm4t(b4, vb + n2 * 32);
                uint32_t bf0[2] = { b4[0], b4[1] };
                uint32_t bf1[2] = { b4[2], b4[3] };
                mma_f16(o[n2 * 2], a, bf0);
                mma_f16(o[n2 * 2 + 1], a, bf1);
            }
        }
        __syncthreads();
    }

    int r0 = wm * 16 + lr, r1 = r0 + 8;
    int qg0 = q0 + r0, qg1 = q0 + r1;
    #pragma unroll
    for (int ni = 0; ni < 8; ni++) {
        int d = h * HD + wn * 64 + ni * 8 + 2 * lc;
        if (qg0 < LTOT)
            *(__half2*)(att + ((size_t)(b * LTOT + qg0)) * DD + d) =
                __floats2half2_rn(o[ni][0], o[ni][1]);
        if (qg1 < LTOT)
            *(__half2*)(att + ((size_t)(b * LTOT + qg1)) * DD + d) =
                __floats2half2_rn(o[ni][2], o[ni][3]);
    }
}

// ---------------- FP16 tensor-core GEMM ----------------
// BM=128, BN=128, BK=32, 256 threads, warp tile 64x32, 2 CTAs/SM.
// 3-stage cp.async pipeline, ONE __syncthreads per K-iter.
// EPI 0: C(half)=acc; 1: C(float)+=acc;
// EPI 3: gate/up interleaved (8-col blocks): C(half)[.. N/2 ..] = gelu(g)*u
#define A_LDB 80
#define B_LDB 272
#define STG_B (128*A_LDB + 32*B_LDB)   // 18944 bytes per stage
#define G5_SMEM (3*STG_B)              // 56832

struct GArgs {
    const __half* A;
    const __half* B[4];
    void*         C[4];
    int M[4], N[4], K[4], ldc[4], seg_len[4], seg_off[4];
    int lda;
};

template <int EPI>
__global__ void __launch_bounds__(256, 2)
gemm_f16(GArgs ga) {
    int z = blockIdx.z;
    int M = ga.M[z], N = ga.N[z], K = ga.K[z];
    int ldc = ga.ldc[z], seg_len = ga.seg_len[z], seg_off = ga.seg_off[z];
    int lda = ga.lda;
    int m0 = blockIdx.y * 128, n0 = blockIdx.x * 128;
    if (m0 >= M || n0 >= N) return;
    const __half* A  = ga.A;
    const __half* Bm = ga.B[z];

    extern __shared__ char smc[];
    uint32_t smb = (uint32_t)__cvta_generic_to_shared(smc);
    int t = threadIdx.x, warp = t >> 5, lane = t & 31;
    int wm = warp >> 2, wn = warp & 3;
    int lr = lane >> 2, lc = lane & 3;

    int ar = t >> 2;
    int ac = t & 3;
    int br = t >> 3;
    int bc = t & 7;
    long offA[2]; int szA[2];
    #pragma unroll
    for (int j = 0; j < 2; j++) {
        int r = m0 + ar + 64 * j;
        bool v = r < M;
        offA[j] = v ? rowmap(r, seg_len, seg_off) * (long)lda : 0;
        szA[j] = v ? 16 : 0;
    }

    auto stage = [&](int k0, int buf) {
        uint32_t Ab = smb + (uint32_t)buf * STG_B;
        #pragma unroll
        for (int j = 0; j < 2; j++)
            cpa16(Ab + (uint32_t)(ar + 64 * j) * A_LDB + ac * 16,
                  A + offA[j] + k0 + ac * 8, szA[j]);
        uint32_t Bb = Ab + 128 * A_LDB;
        #pragma unroll
        for (int j = 0; j < 2; j++)
            cpa16(Bb + (uint32_t)br * B_LDB + (bc + 8 * j) * 16,
                  Bm + (size_t)(k0 + br) * N + n0 + (bc + 8 * j) * 8, 16);
        CP_COMMIT();
    };

    int lrow = (lane & 7) + 8 * ((lane >> 3) & 1);
    int lhi  = (lane >> 4) & 1;

    float acc[4][4][4];
    #pragma unroll
    for (int mi = 0; mi < 4; mi++)
        #pragma unroll
        for (int ni = 0; ni < 4; ni++)
            #pragma unroll
            for (int j = 0; j < 4; j++) acc[mi][ni][j] = 0.f;

    int ntiles = K >> 5;
    stage(0, 0);
    stage(32, 1);

    int buf = 0;
    for (int it = 0; it < ntiles; it++) {
        if (it + 1 < ntiles) { CP_WAIT1(); } else { CP_WAIT0(); }
        __syncthreads();
        if (it + 2 < ntiles) {
            int nb = buf + 2; if (nb >= 3) nb -= 3;
            stage((it + 2) << 5, nb);
        }

        uint32_t As = smb + (uint32_t)buf * STG_B;
        uint32_t Bs = As + 128 * A_LDB;
        #pragma unroll
        for (int kq = 0; kq < 2; kq++) {
            uint32_t af[4][4];
            #pragma unroll
            for (int mi = 0; mi < 4; mi++)
                ldsm4(af[mi], As + (uint32_t)(wm * 64 + mi * 16 + lrow) * A_LDB
                              + kq * 32 + lhi * 16);
            uint32_t bf[4][2];
            #pragma unroll
            for (int n2 = 0; n2 < 2; n2++) {
                uint32_t b4[4];
                ldsm4t(b4, Bs + (uint32_t)(kq * 16 + lrow) * B_LDB
                           + (uint32_t)(wn * 32 + n2 * 16 + lhi * 8) * 2);
                bf[n2 * 2][0] = b4[0]; bf[n2 * 2][1] = b4[1];
                bf[n2 * 2 + 1][0] = b4[2]; bf[n2 * 2 + 1][1] = b4[3];
            }
            #pragma unroll
            for (int mi = 0; mi < 4; mi++)
                #pragma unroll
                for (int ni = 0; ni < 4; ni++)
                    mma_f16(acc[mi][ni], af[mi], bf[ni]);
        }
        if (++buf >= 3) buf = 0;
    }

    // epilogue
    #pragma unroll
    for (int mi = 0; mi < 4; mi++) {
        int rb = m0 + wm * 64 + mi * 16 + lr;
        #pragma unroll
        for (int hh = 0; hh < 2; hh++) {
            int r = rb + hh * 8;
            if (r >= M) continue;
            if (EPI == 3) {
                long base = rowmap(r, seg_len, seg_off) * (long)ldc + ((n0 + wn * 32) >> 1);
                #pragma unroll
                for (int np = 0; np < 2; np++) {
                    float g0 = acc[mi][2 * np][hh * 2 + 0];
                    float g1 = acc[mi][2 * np][hh * 2 + 1];
                    float u0 = acc[mi][2 * np + 1][hh * 2 + 0];
                    float u1 = acc[mi][2 * np + 1][hh * 2 + 1];
                    *(__half2*)((__half*)ga.C[z] + base + np * 8 + lc * 2) =
                        __floats2half2_rn(gelu_tanh(g0) * u0, gelu_tanh(g1) * u1);
                }
            } else {
                long base = rowmap(r, seg_len, seg_off) * (long)ldc + n0;
                #pragma unroll
                for (int ni = 0; ni < 4; ni++) {
                    long p = base + wn * 32 + ni * 8 + lc * 2;
                    float v0 = acc[mi][ni][hh * 2 + 0];
                    float v1 = acc[mi][ni][hh * 2 + 1];
                    if (EPI == 0) {
                        *(__half2*)((__half*)ga.C[z] + p) = __floats2half2_rn(v0, v1);
                    } else {
                        float* C = (float*)ga.C[z];
                        C[p] += v0; C[p + 1] += v1;
                    }
                }
            }
        }
    }
}

// ---------------- host-side launch helper ----------------
struct SubProb {
    const __half* B; void* C;
    int M, N, K, ldc, seg_len, seg_off;
};

static void launch_gemm_multi(int epi, const __half* A, int lda,
                              const SubProb* sp, int nz) {
    GArgs ga;
    ga.A = A; ga.lda = lda;
    int maxN = 0, maxM = 0;
    for (int z = 0; z < nz; z++) {
        ga.B[z] = sp[z].B; ga.C[z] = sp[z].C;
        ga.M[z] = sp[z].M; ga.N[z] = sp[z].N; ga.K[z] = sp[z].K;
        ga.ldc[z] = sp[z].ldc; ga.seg_len[z] = sp[z].seg_len; ga.seg_off[z] = sp[z].seg_off;
        if (sp[z].N > maxN) maxN = sp[z].N;
        if (sp[z].M > maxM) maxM = sp[z].M;
    }
    dim3 grid(maxN / 128, (maxM + 127) / 128, nz);
    if (epi == 0)      gemm_f16<0><<<grid, 256, G5_SMEM>>>(ga);
    else if (epi == 1) gemm_f16<1><<<grid, 256, G5_SMEM>>>(ga);
    else               gemm_f16<3><<<grid, 256, G5_SMEM>>>(ga);
}

extern "C" void kernel_launch(void* const* d_in, const int* in_sizes, int n_in,
                              void* d_out, int out_size) {
    const float* prefix = (const float*)d_in[0];
    const float* suffix = (const float*)d_in[1];
    const float* p_ln1  = (const float*)d_in[4];
    const float* p_ln2  = (const float*)d_in[9];
    const float* e_ln1  = (const float*)d_in[13];
    const float* e_ln2  = (const float*)d_in[18];

    float* h = (float*)d_out;
    __half *n_, *q_, *k_, *v_, *att_, *mlp_, *wt_;
    cudaGetSymbolAddress((void**)&n_,   g_n);
    cudaGetSymbolAddress((void**)&q_,   g_q);
    cudaGetSymbolAddress((void**)&k_,   g_kb);
    cudaGetSymbolAddress((void**)&v_,   g_vb);
    cudaGetSymbolAddress((void**)&att_, g_att);
    cudaGetSymbolAddress((void**)&mlp_, g_mlp);
    cudaGetSymbolAddress((void**)&wt_,  g_wth);

    cudaFuncSetAttribute(attn_f16, cudaFuncAttributeMaxDynamicSharedMemorySize, ATTN_SMEM);
    cudaFuncSetAttribute(gemm_f16<0>, cudaFuncAttributeMaxDynamicSharedMemorySize, G5_SMEM);
    cudaFuncSetAttribute(gemm_f16<1>, cudaFuncAttributeMaxDynamicSharedMemorySize, G5_SMEM);
    cudaFuncSetAttribute(gemm_f16<3>, cudaFuncAttributeMaxDynamicSharedMemorySize, G5_SMEM);

    // ---- weight layout in g_wth (halfs) ----
    // q_p, k_p, v_p, o_p, gu_p(interleaved 2*DD*2MV), d_p,
    // q_e, k_e, v_e, o_e, gu_e(2*DD*2ME), d_e
    long off = 0;
    const __half* wq_p = wt_ + off; long oq_p = off; off += 2L*DD*DD;
    const __half* wk_p = wt_ + off; long ok_p = off; off += 2L*DD*HD;
    const __half* wv_p = wt_ + off; long ov_p = off; off += 2L*DD*HD;
    const __half* wo_p = wt_ + off; long oo_p = off; off += 2L*DD*DD;
    const __half* wgu_p = wt_ + off; long ogu_p = off; off += 2L*DD*2*MV;
    const __half* wd_p = wt_ + off; long od_p = off; off += 2L*MV*DD;
    const __half* wq_e = wt_ + off; long oq_e = off; off += 2L*DD*DD;
    const __half* wk_e = wt_ + off; long ok_e = off; off += 2L*DD*HD;
    const __half* wv_e = wt_ + off; long ov_e = off; off += 2L*DD*HD;
    const __half* wo_e = wt_ + off; long oo_e = off; off += 2L*DD*DD;
    const __half* wgu_e = wt_ + off; long ogu_e = off; off += 2L*DD*2*ME;
    const __half* wd_e = wt_ + off; long od_e = off; off += 2L*ME*DD;

    // plain conversions (10 regions)
    {
        PlainArgs pa;
        const int srcIdx[10] = {5, 6, 7, 8, 12, 14, 15, 16, 17, 21};
        const long doffs[10] = {oq_p, ok_p, ov_p, oo_p, od_p, oq_e, ok_e, ov_e, oo_e, od_e};
        const long cnts[10] = {2L*DD*DD/4, 2L*DD*HD/4, 2L*DD*HD/4, 2L*DD*DD/4, 2L*MV*DD/4,
                               2L*DD*DD/4, 2L*DD*HD/4, 2L*DD*HD/4, 2L*DD*DD/4, 2L*ME*DD/4};
        for (int i = 0; i < 10; i++) {
            pa.src[i] = (const float4*)d_in[srcIdx[i]];
            pa.doff[i] = doffs[i];
            pa.cnt4[i] = cnts[i];
        }
        conv_plain<<<dim3(512, 10, 1), 256>>>(pa, wt_);
    }
    // gate/up interleaved conversions
    conv_gu<<<dim3(512, 1, 2), 256>>>((const float4*)d_in[10], (const float4*)d_in[11],
                                      wt_ + ogu_p, 13 /*log2 MV*/, 2L*DD*MV/4);
    conv_gu<<<dim3(512, 1, 2), 256>>>((const float4*)d_in[19], (const float4*)d_in[20],
                                      wt_ + ogu_e, 12 /*log2 ME*/, 2L*DD*ME/4);

    init_h_kernel<<<NTOK, 256>>>(prefix, suffix, h);

    for (int layer = 0; layer < 2; layer++) {
        size_t lW  = (size_t)layer * DD * DD;
        size_t lKV = (size_t)layer * DD * HD;
        size_t lGUp = (size_t)layer * DD * 2 * MV;
        size_t lGUe = (size_t)layer * DD * 2 * ME;
        size_t lDp = (size_t)layer * MV * DD;
        size_t lDe = (size_t)layer * ME * DD;

        rmsnorm_kernel<<<NTOK, 256>>>(h, (__half2*)n_, p_ln1 + layer * DD, e_ln1 + layer * DD);

        {   // q projection (prefix + suffix)
            SubProb sp[2] = {
                { wq_p + lW, q_, BB*LP, DD, DD, DD, LP, 0 },
                { wq_e + lW, q_, BB*LS, DD, DD, DD, LS, LP } };
            launch_gemm_multi(0, n_, DD, sp, 2);
        }
        {   // k/v projections (4-way)
            SubProb sp[4] = {
                { wk_p + lKV, k_, BB*LP, HD, DD, HD, LP, 0 },
                { wv_p + lKV, v_, BB*LP, HD, DD, HD, LP, 0 },
                { wk_e + lKV, k_, BB*LS, HD, DD, HD, LS, LP },
                { wv_e + lKV, v_, BB*LS, HD, DD, HD, LS, LP } };
            launch_gemm_multi(0, n_, DD, sp, 4);
        }

        rope_kernel<<<NTOK, 256>>>(q_, k_);
        dim3 ag(26, HH, BB);
        attn_f16<<<ag, 256, ATTN_SMEM>>>(q_, k_, v_, att_);

        {   // o projection + residual (into float h)
            SubProb sp[2] = {
                { wo_p + lW, h, BB*LP, DD, DD, DD, LP, 0 },
                { wo_e + lW, h, BB*LS, DD, DD, DD, LS, LP } };
            launch_gemm_multi(1, att_, DD, sp, 2);
        }

        rmsnorm_kernel<<<NTOK, 256>>>(h, (__half2*)n_, p_ln2 + layer * DD, e_ln2 + layer * DD);

        {   // fused gate+up (interleaved) -> act into mlp_
            SubProb sp[2] = {
                { wgu_p + lGUp, mlp_, BB*LP, 2*MV, DD, MV, LP, 0 },
                { wgu_e + lGUe, mlp_, BB*LS, 2*ME, DD, MV, LS, LP } };
            launch_gemm_multi(3, n_, DD, sp, 2);
        }
        {   // down + residual (into float h)
            SubProb sp[2] = {
                { wd_p + lDp, h, BB*LP, DD, MV, DD, LP, 0 },
                { wd_e + lDe, h, BB*LS, DD, ME, DD, LS, LP } };
            launch_gemm_multi(1, mlp_, MV, sp, 2);
        }
    }
}